// round 1
// baseline (speedup 1.0000x reference)
#include <cuda_runtime.h>
#include <math.h>

#define N0 1362944
#define N1 123904
#define N2 11264
#define N3 1024
#define C_IN 128
#define C_HID 256
#define C_OUT 47

// ---------------- scratch (device globals; no allocation allowed) ----------
__device__ float g_agg0[N1 * C_IN];     // 63.4 MB
__device__ float g_cnt0[N1];
__device__ float g_h0[N1 * C_HID];      // 126.9 MB
__device__ float g_agg1[N2 * C_HID];    // 11.5 MB
__device__ float g_cnt1[N2];
__device__ float g_h1[N2 * C_HID];      // 11.5 MB
__device__ float g_agg2[N3 * C_HID];    // 1 MB
__device__ float g_cnt2[N3];

// ---------------- helpers ---------------------------------------------------
__device__ __forceinline__ void red_add_v4(float* addr, float4 v) {
    asm volatile("red.global.add.v4.f32 [%0], {%1,%2,%3,%4};"
                 :: "l"(addr), "f"(v.x), "f"(v.y), "f"(v.z), "f"(v.w)
                 : "memory");
}

__device__ __forceinline__ unsigned long long pk2(float lo, float hi) {
    unsigned long long r;
    asm("mov.b64 %0, {%1, %2};"
        : "=l"(r) : "r"(__float_as_uint(lo)), "r"(__float_as_uint(hi)));
    return r;
}
__device__ __forceinline__ void upk2(unsigned long long p, float& lo, float& hi) {
    unsigned int a, b;
    asm("mov.b64 {%0, %1}, %2;" : "=r"(a), "=r"(b) : "l"(p));
    lo = __uint_as_float(a);
    hi = __uint_as_float(b);
}
__device__ __forceinline__ void fma2(unsigned long long& d,
                                     unsigned long long a, unsigned long long b) {
    // packed 2x fp32 FMA (Blackwell FFMA2) — only reachable via PTX
    asm("fma.rn.f32x2 %0, %1, %2, %0;" : "+l"(d) : "l"(a), "l"(b));
}

// ---------------- zero ------------------------------------------------------
__global__ void zero_kernel(float4* __restrict__ p, int n4) {
    int i = blockIdx.x * blockDim.x + threadIdx.x;
    int stride = gridDim.x * blockDim.x;
    float4 z = make_float4(0.f, 0.f, 0.f, 0.f);
    for (; i < n4; i += stride) p[i] = z;
}

// ---------------- scatter-add (mean numerator + counts) --------------------
// one warp per edge; vectorized 128-bit reductions into agg[tgt]
template <int C>
__global__ void scatter_kernel(const float* __restrict__ feat,
                               const int* __restrict__ ei, int E,
                               float* __restrict__ agg, float* __restrict__ cnt) {
    int warp = (blockIdx.x * blockDim.x + threadIdx.x) >> 5;
    int lane = threadIdx.x & 31;
    if (warp >= E) return;
    int s = __ldg(&ei[warp]);
    int t = __ldg(&ei[E + warp]);
    const float4* srow = reinterpret_cast<const float4*>(feat + (size_t)s * C);
    float* arow = agg + (size_t)t * C;
#pragma unroll
    for (int j = lane; j < C / 4; j += 32) {
        float4 v = __ldg(&srow[j]);
        red_add_v4(arow + 4 * j, v);
    }
    if (lane == 0) atomicAdd(&cnt[t], 1.0f);
}

// ---------------- fused SAGE GEMM -------------------------------------------
// out = act( (agg/max(cnt,1)) @ Wl + xt @ Wr + b )
// BM=BN=128, BK=8, 256 threads, 8x8 microtile via packed f32x2 FMAs.
// Requires M % 128 == 0, N % 128 == 0, K % 8 == 0 (true for layers 0,1).
template <bool RELU>
__global__ __launch_bounds__(256) void sage_gemm(
    const float* __restrict__ agg, const float* __restrict__ cnt,
    const float* __restrict__ xt,
    const float* __restrict__ Wl, const float* __restrict__ Wr,
    const float* __restrict__ bias,
    float* __restrict__ out, int M, int K, int N) {
    constexpr int BM = 128, BN = 128, BK = 8;
    __shared__ float As[BK][BM];
    __shared__ float Bs[BK][BN];
    __shared__ float sInv[BM];

    int tid = threadIdx.x;
    int m0 = blockIdx.y * BM;
    int n0 = blockIdx.x * BN;
    int tx = tid & 15;
    int ty = tid >> 4;

    if (tid < BM) sInv[tid] = 1.0f / fmaxf(cnt[m0 + tid], 1.0f);

    unsigned long long acc[8][4];
#pragma unroll
    for (int i = 0; i < 8; i++)
#pragma unroll
        for (int j = 0; j < 4; j++) acc[i][j] = 0ull;

    int lm = tid >> 1;           // A load: row within tile
    int lk = (tid & 1) * 4;      // A load: col within BK
    int bkr = tid >> 5;          // B load: row within BK
    int bnc = (tid & 31) * 4;    // B load: col within BN

    __syncthreads();  // sInv ready

    int nchunks = (2 * K) / BK;
    for (int c = 0; c < nchunks; c++) {
        int kk = c * BK;
        bool phA = (kk < K);
        const float* Asrc = phA ? agg : xt;
        const float* Wsrc = phA ? Wl : Wr;
        int kb = phA ? kk : kk - K;

        float4 av = *reinterpret_cast<const float4*>(
            Asrc + (size_t)(m0 + lm) * K + kb + lk);
        float sc = phA ? sInv[lm] : 1.0f;
        float4 bv = *reinterpret_cast<const float4*>(
            Wsrc + (size_t)(kb + bkr) * N + n0 + bnc);

        __syncthreads();  // WAR guard vs previous compute
        As[lk + 0][lm] = av.x * sc;
        As[lk + 1][lm] = av.y * sc;
        As[lk + 2][lm] = av.z * sc;
        As[lk + 3][lm] = av.w * sc;
        *reinterpret_cast<float4*>(&Bs[bkr][bnc]) = bv;
        __syncthreads();

#pragma unroll
        for (int k = 0; k < BK; k++) {
            float4 a0 = *reinterpret_cast<const float4*>(&As[k][ty * 8]);
            float4 a1 = *reinterpret_cast<const float4*>(&As[k][ty * 8 + 4]);
            const unsigned long long* bp =
                reinterpret_cast<const unsigned long long*>(&Bs[k][tx * 8]);
            unsigned long long b01 = bp[0], b23 = bp[1], b45 = bp[2], b67 = bp[3];
            float av8[8] = {a0.x, a0.y, a0.z, a0.w, a1.x, a1.y, a1.z, a1.w};
#pragma unroll
            for (int i = 0; i < 8; i++) {
                unsigned long long ap = pk2(av8[i], av8[i]);
                fma2(acc[i][0], ap, b01);
                fma2(acc[i][1], ap, b23);
                fma2(acc[i][2], ap, b45);
                fma2(acc[i][3], ap, b67);
            }
        }
    }

    // epilogue
    int row0 = m0 + ty * 8;
    int col0 = n0 + tx * 8;
    float bb[8];
#pragma unroll
    for (int j = 0; j < 8; j++) bb[j] = bias[col0 + j];
#pragma unroll
    for (int i = 0; i < 8; i++) {
        float v[8];
#pragma unroll
        for (int j = 0; j < 4; j++) upk2(acc[i][j], v[2 * j], v[2 * j + 1]);
#pragma unroll
        for (int j = 0; j < 8; j++) {
            v[j] += bb[j];
            if (RELU) v[j] = fmaxf(v[j], 0.0f);
        }
        float* orow = out + (size_t)(row0 + i) * N + col0;
        *reinterpret_cast<float4*>(orow) = make_float4(v[0], v[1], v[2], v[3]);
        *reinterpret_cast<float4*>(orow + 4) = make_float4(v[4], v[5], v[6], v[7]);
    }
}

// ---------------- final layer: small GEMM + log_softmax fused ---------------
// one block per output row (M=1024), 64 threads
__global__ void final_kernel(const float* __restrict__ agg,
                             const float* __restrict__ cnt,
                             const float* __restrict__ xt,
                             const float* __restrict__ Wl,
                             const float* __restrict__ Wr,
                             const float* __restrict__ bias,
                             float* __restrict__ out) {
    __shared__ float sA[2 * C_HID];
    __shared__ float sred[64];
    int m = blockIdx.x;
    int tid = threadIdx.x;

    float invc = 1.0f / fmaxf(cnt[m], 1.0f);
    for (int j = tid; j < C_HID; j += 64) {
        sA[j] = agg[(size_t)m * C_HID + j] * invc;
        sA[C_HID + j] = xt[(size_t)m * C_HID + j];
    }
    __syncthreads();

    float z = -1e30f;
    if (tid < C_OUT) {
        float a = bias[tid];
        for (int k = 0; k < C_HID; k++) a = fmaf(sA[k], Wl[k * C_OUT + tid], a);
        for (int k = 0; k < C_HID; k++)
            a = fmaf(sA[C_HID + k], Wr[k * C_OUT + tid], a);
        z = a;
    }

    sred[tid] = z;
    __syncthreads();
    for (int s = 32; s > 0; s >>= 1) {
        if (tid < s) sred[tid] = fmaxf(sred[tid], sred[tid + s]);
        __syncthreads();
    }
    float mx = sred[0];
    __syncthreads();
    sred[tid] = (tid < C_OUT) ? expf(z - mx) : 0.0f;
    __syncthreads();
    for (int s = 32; s > 0; s >>= 1) {
        if (tid < s) sred[tid] += sred[tid + s];
        __syncthreads();
    }
    float lse = logf(sred[0]) + mx;
    if (tid < C_OUT) out[m * C_OUT + tid] = z - lse;
}

// ---------------- launch -----------------------------------------------------
extern "C" void kernel_launch(void* const* d_in, const int* in_sizes, int n_in,
                              void* d_out, int out_size) {
    const float* x   = (const float*)d_in[0];
    const int*  ei0  = (const int*)d_in[1];
    const int*  ei1  = (const int*)d_in[2];
    const int*  ei2  = (const int*)d_in[3];
    const float* Wl0 = (const float*)d_in[4];
    const float* Wr0 = (const float*)d_in[5];
    const float* b0  = (const float*)d_in[6];
    const float* Wl1 = (const float*)d_in[7];
    const float* Wr1 = (const float*)d_in[8];
    const float* b1  = (const float*)d_in[9];
    const float* Wl2 = (const float*)d_in[10];
    const float* Wr2 = (const float*)d_in[11];
    const float* b2  = (const float*)d_in[12];

    int E0 = in_sizes[1] / 2;
    int E1 = in_sizes[2] / 2;
    int E2 = in_sizes[3] / 2;

    float *agg0, *cnt0, *h0, *agg1, *cnt1, *h1, *agg2, *cnt2;
    cudaGetSymbolAddress((void**)&agg0, g_agg0);
    cudaGetSymbolAddress((void**)&cnt0, g_cnt0);
    cudaGetSymbolAddress((void**)&h0,   g_h0);
    cudaGetSymbolAddress((void**)&agg1, g_agg1);
    cudaGetSymbolAddress((void**)&cnt1, g_cnt1);
    cudaGetSymbolAddress((void**)&h1,   g_h1);
    cudaGetSymbolAddress((void**)&agg2, g_agg2);
    cudaGetSymbolAddress((void**)&cnt2, g_cnt2);

    float* out = (float*)d_out;

    // ---- layer 0 ----
    {
        int n4 = N1 * C_IN / 4;
        zero_kernel<<<(n4 + 255) / 256, 256>>>((float4*)agg0, n4);
        zero_kernel<<<(N1 / 4 + 255) / 256, 256>>>((float4*)cnt0, N1 / 4);
        scatter_kernel<C_IN><<<(E0 + 7) / 8, 256>>>(x, ei0, E0, agg0, cnt0);
        sage_gemm<true><<<dim3(C_HID / 128, N1 / 128), 256>>>(
            agg0, cnt0, x, Wl0, Wr0, b0, h0, N1, C_IN, C_HID);
    }
    // ---- layer 1 ----
    {
        int n4 = N2 * C_HID / 4;
        zero_kernel<<<(n4 + 255) / 256, 256>>>((float4*)agg1, n4);
        zero_kernel<<<(N2 / 4 + 255) / 256, 256>>>((float4*)cnt1, N2 / 4);
        scatter_kernel<C_HID><<<(E1 + 7) / 8, 256>>>(h0, ei1, E1, agg1, cnt1);
        sage_gemm<true><<<dim3(C_HID / 128, N2 / 128), 256>>>(
            agg1, cnt1, h0, Wl1, Wr1, b1, h1, N2, C_HID, C_HID);
    }
    // ---- layer 2 + log_softmax ----
    {
        int n4 = N3 * C_HID / 4;
        zero_kernel<<<(n4 + 255) / 256, 256>>>((float4*)agg2, n4);
        zero_kernel<<<(N3 / 4 + 255) / 256, 256>>>((float4*)cnt2, N3 / 4);
        scatter_kernel<C_HID><<<(E2 + 7) / 8, 256>>>(h1, ei2, E2, agg2, cnt2);
        final_kernel<<<N3, 64>>>(agg2, cnt2, h1, Wl2, Wr2, b2, out);
    }
}

// round 4
// speedup vs baseline: 1.2918x; 1.2918x over previous
#include <cuda_runtime.h>
#include <cuda_bf16.h>
#include <math.h>
#include <stdint.h>

#define N0 1362944
#define N1 123904
#define N2 11264
#define N3 1024
#define C_IN 128
#define C_HID 256
#define C_OUT 47

// ---------------- scratch (device globals; no allocation allowed) ----------
__device__ float g_agg0[N1 * C_IN];
__device__ float g_cnt0[N1];
__device__ float g_h0[N1 * C_HID];
__device__ float g_agg1[N2 * C_HID];
__device__ float g_cnt1[N2];
__device__ float g_h1[N2 * C_HID];
__device__ float g_agg2[N3 * C_HID];
__device__ float g_cnt2[N3];
// pre-fragmented bf16 weights: per 64-fp32-k chunk: [sub2][kstep4][ntile32][lane32]*8B
__device__ uint8_t g_wB0[4 * 65536];   // layer0: 4 chunks
__device__ uint8_t g_wB1[8 * 65536];   // layer1: 8 chunks

// ---------------- helpers ---------------------------------------------------
__device__ __forceinline__ void red_add_v4(float* addr, float4 v) {
    asm volatile("red.global.add.v4.f32 [%0], {%1,%2,%3,%4};"
                 :: "l"(addr), "f"(v.x), "f"(v.y), "f"(v.z), "f"(v.w)
                 : "memory");
}
__device__ __forceinline__ uint32_t smem_u32(const void* p) {
    uint32_t a;
    asm("{ .reg .u64 t; cvta.to.shared.u64 t, %1; cvt.u32.u64 %0, t; }"
        : "=r"(a) : "l"(p));
    return a;
}
__device__ __forceinline__ void cp_async16(uint32_t dst, const void* src) {
    asm volatile("cp.async.ca.shared.global [%0], [%1], 16;"
                 :: "r"(dst), "l"(src) : "memory");
}
__device__ __forceinline__ void mma16816(float* d, const uint4& a, const uint2& b) {
    asm volatile(
        "mma.sync.aligned.m16n8k16.row.col.f32.bf16.bf16.f32 "
        "{%0,%1,%2,%3}, {%4,%5,%6,%7}, {%8,%9}, {%0,%1,%2,%3};"
        : "+f"(d[0]), "+f"(d[1]), "+f"(d[2]), "+f"(d[3])
        : "r"(a.x), "r"(a.y), "r"(a.z), "r"(a.w), "r"(b.x), "r"(b.y));
}

// ---------------- zero ------------------------------------------------------
__global__ void zero_kernel(float4* __restrict__ p, int n4) {
    int i = blockIdx.x * blockDim.x + threadIdx.x;
    int stride = gridDim.x * blockDim.x;
    float4 z = make_float4(0.f, 0.f, 0.f, 0.f);
    for (; i < n4; i += stride) p[i] = z;
}

// ---------------- scatter-add ------------------------------------------------
template <int C>
__global__ void scatter_kernel(const float* __restrict__ feat,
                               const int* __restrict__ ei, int E,
                               float* __restrict__ agg, float* __restrict__ cnt) {
    int warp = (blockIdx.x * blockDim.x + threadIdx.x) >> 5;
    int lane = threadIdx.x & 31;
    if (warp >= E) return;
    int s = __ldg(&ei[warp]);
    int t = __ldg(&ei[E + warp]);
    const float4* srow = reinterpret_cast<const float4*>(feat + (size_t)s * C);
    float* arow = agg + (size_t)t * C;
#pragma unroll
    for (int j = lane; j < C / 4; j += 32) {
        float4 v = __ldg(&srow[j]);
        red_add_v4(arow + 4 * j, v);
    }
    if (lane == 0) atomicAdd(&cnt[t], 1.0f);
}

// ---------------- weight prep: stack, split bf16 hi/lo, fragment-pack -------
// W' = [Wl; Wr] (2K x 256). One thread per (k-pair, n).
// Fragment slot for element (k_in_chunk kk, n):
//   kstep=kk>>4, kk16=kk&15, t=(kk16>>1)&3, regk=kk16>>3, g=n&7, ntile=n>>3
//   off = chunk*65536 + sub*32768 + kstep*8192 + ntile*256 + (g*4+t)*8 + regk*4
__global__ void prep_w(const float* __restrict__ Wl, const float* __restrict__ Wr,
                       int K, uint8_t* __restrict__ wB) {
    int idx = blockIdx.x * blockDim.x + threadIdx.x;
    if (idx >= K * 256) return;          // K pairs over 2K stacked rows
    int kp = idx >> 8, n = idx & 255;
    int k = kp * 2;
    const float* W = (k < K) ? Wl : Wr;
    int kb = (k < K) ? k : k - K;
    float v0 = W[kb * 256 + n];
    float v1 = W[(kb + 1) * 256 + n];
    __nv_bfloat162 h = __floats2bfloat162_rn(v0, v1);
    float2 f = __bfloat1622float2(h);
    __nv_bfloat162 l = __floats2bfloat162_rn(v0 - f.x, v1 - f.y);

    int chunk = k >> 6;
    int kk = k & 63;
    int kstep = kk >> 4, kk16 = kk & 15;
    int t = (kk16 >> 1) & 3, regk = kk16 >> 3;
    int g = n & 7, ntile = n >> 3;
    size_t off = (size_t)chunk * 65536 + (size_t)kstep * 8192 + ntile * 256 +
                 (g * 4 + t) * 8 + regk * 4;
    *(uint32_t*)(wB + off) = *(uint32_t*)&h;           // sub0 = hi
    *(uint32_t*)(wB + off + 32768) = *(uint32_t*)&l;   // sub1 = lo
}

// ---------------- HMMA fused SAGE GEMM ---------------------------------------
// out[:,n0:n0+128] = act( [agg/max(cnt,1) | xt] @ W' + b )
// split-bf16 products: Ah*Wh + Al*Wh + Ah*Wl. CTA tile 128x128, 8 warps 2x4,
// warp tile 64x32. K in chunks of 64 fp32; double-buffered SMEM stages of
// 64KB (A frag-packed 32KB + B frag-packed 32KB). cp.async for B, reg
// prefetch for A.
template <int K, bool RELU>
__global__ __launch_bounds__(256) void mma_gemm(
    const float* __restrict__ agg, const float* __restrict__ cnt,
    const float* __restrict__ xt, const uint8_t* __restrict__ wB,
    const float* __restrict__ bias, float* __restrict__ out) {
    constexpr int CH = (2 * K) / 64;
    extern __shared__ char sm[];
    __shared__ float sInv[128];
    __shared__ float sBias[128];

    const int tid = threadIdx.x;
    const int lane = tid & 31;
    const int wid = tid >> 5;
    const int warp_m = wid & 1;
    const int warp_n = wid >> 1;
    const int m0 = blockIdx.y * 128;
    const int n0 = blockIdx.x * 128;
    const int ntile0 = n0 >> 3;

    if (tid < 128) {
        sInv[tid] = 1.0f / fmaxf(cnt[m0 + tid], 1.0f);
        sBias[tid] = bias[n0 + tid];
    }

    const int row = tid >> 1;
    const int kcol0 = (tid & 1) * 32;
    const int mtile = row >> 4;
    const int gr = row & 7;
    const int regm = (row >> 3) & 1;

    // ---- A prefetch chunk 0 ----
    float4 ar[8];
    {
        const float* src = agg;  // chunk 0 always phase A
        const float4* p = (const float4*)(src + (size_t)(m0 + row) * K + kcol0);
#pragma unroll
        for (int i = 0; i < 8; i++) ar[i] = p[i];
    }
    // ---- B cp.async chunk 0 -> stage 0 ----
    {
        char* dst = sm + 32768 + tid * 16;
        const uint8_t* src = wB + ntile0 * 256 + tid * 16;
#pragma unroll
        for (int blk = 0; blk < 8; blk++)
            cp_async16(smem_u32(dst + blk * 4096), src + blk * 8192);
        asm volatile("cp.async.commit_group;");
    }

    float acc[4][4][4];
#pragma unroll
    for (int a = 0; a < 4; a++)
#pragma unroll
        for (int b = 0; b < 4; b++)
#pragma unroll
            for (int c = 0; c < 4; c++) acc[a][b][c] = 0.0f;

    __syncthreads();  // sInv ready

    for (int c = 0; c < CH; c++) {
        const int s = c & 1;
        char* As = sm + s * 65536;
        char* Bs = sm + s * 65536 + 32768;

        // ---- convert + store A into fragment layout ----
        const float sc = (c * 64 < K) ? sInv[row] : 1.0f;
#pragma unroll
        for (int i = 0; i < 8; i++) {
            float x0 = ar[i].x * sc, x1 = ar[i].y * sc;
            float x2 = ar[i].z * sc, x3 = ar[i].w * sc;
#pragma unroll
            for (int j = 0; j < 2; j++) {
                float lo = j ? x2 : x0, hi = j ? x3 : x1;
                int k = kcol0 + 4 * i + 2 * j;
                int ks = k >> 4, kk16 = k & 15;
                int t = (kk16 >> 1) & 3, regk = kk16 >> 3;
                int off = ((ks * 8 + mtile) * 32 + (gr * 4 + t)) * 16 +
                          (regm + 2 * regk) * 4;
                __nv_bfloat162 h = __floats2bfloat162_rn(lo, hi);
                float2 f = __bfloat1622float2(h);
                __nv_bfloat162 l = __floats2bfloat162_rn(lo - f.x, hi - f.y);
                *(uint32_t*)(As + off) = *(uint32_t*)&h;
                *(uint32_t*)(As + 16384 + off) = *(uint32_t*)&l;
            }
        }

        // ---- prefetch next A ----
        if (c + 1 < CH) {
            int cc = (c + 1) * 64;
            bool ph = cc < K;
            const float* src = ph ? agg : xt;
            int kb = ph ? cc : cc - K;
            const float4* p =
                (const float4*)(src + (size_t)(m0 + row) * K + kb + kcol0);
#pragma unroll
            for (int i = 0; i < 8; i++) ar[i] = p[i];
        }
        // ---- cp.async next B ----
        if (c + 1 < CH) {
            char* dst = sm + (s ^ 1) * 65536 + 32768 + tid * 16;
            const uint8_t* src =
                wB + (size_t)(c + 1) * 65536 + ntile0 * 256 + tid * 16;
#pragma unroll
            for (int blk = 0; blk < 8; blk++)
                cp_async16(smem_u32(dst + blk * 4096), src + blk * 8192);
            asm volatile("cp.async.commit_group;");
            asm volatile("cp.async.wait_group 1;");
        } else {
            asm volatile("cp.async.wait_group 0;");
        }
        __syncthreads();

        // ---- MMA: products (Ah,Wh), (Al,Wh), (Ah,Wl) ----
#pragma unroll
        for (int p = 0; p < 3; p++) {
            const char* Ab = As + ((p == 1) ? 16384 : 0);
            const char* Bb = Bs + ((p == 2) ? 16384 : 0);
#pragma unroll
            for (int ks = 0; ks < 4; ks++) {
                uint4 a[4];
#pragma unroll
                for (int mt = 0; mt < 4; mt++)
                    a[mt] = *(const uint4*)(
                        Ab + ((ks * 8 + warp_m * 4 + mt) * 32 + lane) * 16);
#pragma unroll
                for (int nt = 0; nt < 4; nt++) {
                    uint2 b = *(const uint2*)(
                        Bb + ((ks * 16 + warp_n * 4 + nt) * 32 + lane) * 8);
#pragma unroll
                    for (int mt = 0; mt < 4; mt++) mma16816(acc[mt][nt], a[mt], b);
                }
            }
        }
        __syncthreads();
    }

    // ---- epilogue ----
    const int tg = lane >> 2;
    const int tt = lane & 3;
#pragma unroll
    for (int mt = 0; mt < 4; mt++) {
        int r0 = m0 + warp_m * 64 + mt * 16 + tg;
#pragma unroll
        for (int nt = 0; nt < 4; nt++) {
            int ci = warp_n * 32 + nt * 8 + tt * 2;
            float b0v = sBias[ci], b1v = sBias[ci + 1];
            float v0 = acc[mt][nt][0] + b0v;
            float v1 = acc[mt][nt][1] + b1v;
            float v2 = acc[mt][nt][2] + b0v;
            float v3 = acc[mt][nt][3] + b1v;
            if (RELU) {
                v0 = fmaxf(v0, 0.f); v1 = fmaxf(v1, 0.f);
                v2 = fmaxf(v2, 0.f); v3 = fmaxf(v3, 0.f);
            }
            *(float2*)(out + (size_t)r0 * 256 + n0 + ci) = make_float2(v0, v1);
            *(float2*)(out + (size_t)(r0 + 8) * 256 + n0 + ci) =
                make_float2(v2, v3);
        }
    }
}

// ---------------- final layer: small GEMM + log_softmax fused ---------------
__global__ void final_kernel(const float* __restrict__ agg,
                             const float* __restrict__ cnt,
                             const float* __restrict__ xt,
                             const float* __restrict__ Wl,
                             const float* __restrict__ Wr,
                             const float* __restrict__ bias,
                             float* __restrict__ out) {
    __shared__ float sA[2 * C_HID];
    __shared__ float sred[64];
    int m = blockIdx.x;
    int tid = threadIdx.x;

    float invc = 1.0f / fmaxf(cnt[m], 1.0f);
    for (int j = tid; j < C_HID; j += 64) {
        sA[j] = agg[(size_t)m * C_HID + j] * invc;
        sA[C_HID + j] = xt[(size_t)m * C_HID + j];
    }
    __syncthreads();

    float z = -1e30f;
    if (tid < C_OUT) {
        float a = bias[tid];
        for (int k = 0; k < C_HID; k++) a = fmaf(sA[k], Wl[k * C_OUT + tid], a);
        for (int k = 0; k < C_HID; k++)
            a = fmaf(sA[C_HID + k], Wr[k * C_OUT + tid], a);
        z = a;
    }

    sred[tid] = z;
    __syncthreads();
    for (int s = 32; s > 0; s >>= 1) {
        if (tid < s) sred[tid] = fmaxf(sred[tid], sred[tid + s]);
        __syncthreads();
    }
    float mx = sred[0];
    __syncthreads();
    sred[tid] = (tid < C_OUT) ? expf(z - mx) : 0.0f;
    __syncthreads();
    for (int s = 32; s > 0; s >>= 1) {
        if (tid < s) sred[tid] += sred[tid + s];
        __syncthreads();
    }
    float lse = logf(sred[0]) + mx;
    if (tid < C_OUT) out[m * C_OUT + tid] = z - lse;
}

// ---------------- launch -----------------------------------------------------
extern "C" void kernel_launch(void* const* d_in, const int* in_sizes, int n_in,
                              void* d_out, int out_size) {
    const float* x   = (const float*)d_in[0];
    const int*  ei0  = (const int*)d_in[1];
    const int*  ei1  = (const int*)d_in[2];
    const int*  ei2  = (const int*)d_in[3];
    const float* Wl0 = (const float*)d_in[4];
    const float* Wr0 = (const float*)d_in[5];
    const float* b0  = (const float*)d_in[6];
    const float* Wl1 = (const float*)d_in[7];
    const float* Wr1 = (const float*)d_in[8];
    const float* b1  = (const float*)d_in[9];
    const float* Wl2 = (const float*)d_in[10];
    const float* Wr2 = (const float*)d_in[11];
    const float* b2  = (const float*)d_in[12];

    int E0 = in_sizes[1] / 2;
    int E1 = in_sizes[2] / 2;
    int E2 = in_sizes[3] / 2;

    float *agg0, *cnt0, *h0, *agg1, *cnt1, *h1, *agg2, *cnt2;
    uint8_t *wB0, *wB1;
    cudaGetSymbolAddress((void**)&agg0, g_agg0);
    cudaGetSymbolAddress((void**)&cnt0, g_cnt0);
    cudaGetSymbolAddress((void**)&h0,   g_h0);
    cudaGetSymbolAddress((void**)&agg1, g_agg1);
    cudaGetSymbolAddress((void**)&cnt1, g_cnt1);
    cudaGetSymbolAddress((void**)&h1,   g_h1);
    cudaGetSymbolAddress((void**)&agg2, g_agg2);
    cudaGetSymbolAddress((void**)&cnt2, g_cnt2);
    cudaGetSymbolAddress((void**)&wB0,  g_wB0);
    cudaGetSymbolAddress((void**)&wB1,  g_wB1);

    const int SMEM_MM = 2 * 65536;
    cudaFuncSetAttribute(mma_gemm<C_IN, true>,
                         cudaFuncAttributeMaxDynamicSharedMemorySize, SMEM_MM);
    cudaFuncSetAttribute(mma_gemm<C_HID, true>,
                         cudaFuncAttributeMaxDynamicSharedMemorySize, SMEM_MM);

    float* out = (float*)d_out;

    // weight prep (independent of data path)
    prep_w<<<(C_IN * 256 + 255) / 256, 256>>>(Wl0, Wr0, C_IN, wB0);
    prep_w<<<(C_HID * 256 + 255) / 256, 256>>>(Wl1, Wr1, C_HID, wB1);

    // ---- layer 0 ----
    {
        int n4 = N1 * C_IN / 4;
        zero_kernel<<<(n4 + 255) / 256, 256>>>((float4*)agg0, n4);
        zero_kernel<<<(N1 / 4 + 255) / 256, 256>>>((float4*)cnt0, N1 / 4);
        scatter_kernel<C_IN><<<(E0 + 7) / 8, 256>>>(x, ei0, E0, agg0, cnt0);
        mma_gemm<C_IN, true><<<dim3(2, N1 / 128), 256, SMEM_MM>>>(
            agg0, cnt0, x, wB0, b0, h0);
    }
    // ---- layer 1 ----
    {
        int n4 = N2 * C_HID / 4;
        zero_kernel<<<(n4 + 255) / 256, 256>>>((float4*)agg1, n4);
        zero_kernel<<<(N2 / 4 + 255) / 256, 256>>>((float4*)cnt1, N2 / 4);
        scatter_kernel<C_HID><<<(E1 + 7) / 8, 256>>>(h0, ei1, E1, agg1, cnt1);
        mma_gemm<C_HID, true><<<dim3(2, N2 / 128), 256, SMEM_MM>>>(
            agg1, cnt1, h0, wB1, b1, h1);
    }
    // ---- layer 2 + log_softmax ----
    {
        int n4 = N3 * C_HID / 4;
        zero_kernel<<<(n4 + 255) / 256, 256>>>((float4*)agg2, n4);
        zero_kernel<<<(N3 / 4 + 255) / 256, 256>>>((float4*)cnt2, N3 / 4);
        scatter_kernel<C_HID><<<(E2 + 7) / 8, 256>>>(h1, ei2, E2, agg2, cnt2);
        final_kernel<<<N3, 64>>>(agg2, cnt2, h1, Wl2, Wr2, b2, out);
    }
}

// round 5
// speedup vs baseline: 1.4292x; 1.1063x over previous
#include <cuda_runtime.h>
#include <cuda_bf16.h>
#include <math.h>
#include <stdint.h>

#define N0 1362944
#define N1 123904
#define N2 11264
#define N3 1024
#define C_IN 128
#define C_HID 256
#define C_OUT 47

// ---------------- scratch (device globals; no allocation allowed) ----------
__device__ float g_agg0[N1 * C_IN];
__device__ float g_cnt0[N1];
__device__ float g_h0[N1 * C_HID];
__device__ float g_agg1[N2 * C_HID];
__device__ float g_cnt1[N2];
__device__ float g_h1[N2 * C_HID];
__device__ float g_agg2[N3 * C_HID];
__device__ float g_cnt2[N3];
// pre-fragmented bf16 weights: per 64-fp32-k chunk (64KB contiguous):
//   [hi 32KB: kstep4 x (ntile32 x lane32 x 8B)][lo 32KB: same]
__device__ uint8_t g_wB0[4 * 65536];   // layer0: 4 chunks
__device__ uint8_t g_wB1[8 * 65536];   // layer1: 8 chunks

// ---------------- helpers ---------------------------------------------------
__device__ __forceinline__ void red_add_v4(float* addr, float4 v) {
    asm volatile("red.global.add.v4.f32 [%0], {%1,%2,%3,%4};"
                 :: "l"(addr), "f"(v.x), "f"(v.y), "f"(v.z), "f"(v.w)
                 : "memory");
}
__device__ __forceinline__ uint32_t smem_u32(const void* p) {
    uint32_t a;
    asm("{ .reg .u64 t; cvta.to.shared.u64 t, %1; cvt.u32.u64 %0, t; }"
        : "=r"(a) : "l"(p));
    return a;
}
__device__ __forceinline__ void cp_async16(uint32_t dst, const void* src) {
    asm volatile("cp.async.ca.shared.global [%0], [%1], 16;"
                 :: "r"(dst), "l"(src) : "memory");
}
__device__ __forceinline__ void mma16816(float* d, const uint4& a, const uint2& b) {
    asm volatile(
        "mma.sync.aligned.m16n8k16.row.col.f32.bf16.bf16.f32 "
        "{%0,%1,%2,%3}, {%4,%5,%6,%7}, {%8,%9}, {%0,%1,%2,%3};"
        : "+f"(d[0]), "+f"(d[1]), "+f"(d[2]), "+f"(d[3])
        : "r"(a.x), "r"(a.y), "r"(a.z), "r"(a.w), "r"(b.x), "r"(b.y));
}

// ---------------- zero ------------------------------------------------------
__global__ void zero_kernel(float4* __restrict__ p, int n4) {
    int i = blockIdx.x * blockDim.x + threadIdx.x;
    int stride = gridDim.x * blockDim.x;
    float4 z = make_float4(0.f, 0.f, 0.f, 0.f);
    for (; i < n4; i += stride) p[i] = z;
}

// ---------------- scatter-add: 4 edges per warp, MLP=4 ----------------------
template <int C>
__global__ void scatter_kernel(const float* __restrict__ feat,
                               const int* __restrict__ ei, int E,
                               float* __restrict__ agg, float* __restrict__ cnt) {
    constexpr int R = C / 128;  // float4s per lane per row
    int warp = (blockIdx.x * blockDim.x + threadIdx.x) >> 5;
    int lane = threadIdx.x & 31;
    int base = warp * 4;
    if (base >= E) return;
    int nv = min(4, E - base);
    int se = (lane < nv) ? __ldg(&ei[base + lane]) : 0;
    int te = (lane < nv) ? __ldg(&ei[E + base + lane]) : 0;

    float4 v[4][R];
#pragma unroll
    for (int j = 0; j < 4; j++) {
        int s = __shfl_sync(0xffffffffu, se, j);
        const float4* p = (const float4*)(feat + (size_t)s * C) + lane;
        if (j < nv) {
#pragma unroll
            for (int r = 0; r < R; r++) v[j][r] = __ldg(p + 32 * r);
        }
    }
#pragma unroll
    for (int j = 0; j < 4; j++) {
        int t = __shfl_sync(0xffffffffu, te, j);
        float* arow = agg + (size_t)t * C + lane * 4;
        if (j < nv) {
#pragma unroll
            for (int r = 0; r < R; r++) red_add_v4(arow + 128 * r, v[j][r]);
        }
    }
    if (lane < nv) atomicAdd(&cnt[te], 1.0f);
}

// ---------------- weight prep: stack, split bf16 hi/lo, fragment-pack -------
// W' = [Wl; Wr] (2K x 256). One thread per (k-pair, n).
// Fragment slot for element (k_in_chunk kk, n):
//   kstep=kk>>4, kk16=kk&15, t=(kk16>>1)&3, regk=kk16>>3, g=n&7, ntile=n>>3
//   off = chunk*65536 + sub*32768 + kstep*8192 + ntile*256 + (g*4+t)*8 + regk*4
__global__ void prep_w(const float* __restrict__ Wl, const float* __restrict__ Wr,
                       int K, uint8_t* __restrict__ wB) {
    int idx = blockIdx.x * blockDim.x + threadIdx.x;
    if (idx >= K * 256) return;          // K pairs over 2K stacked rows
    int kp = idx >> 8, n = idx & 255;
    int k = kp * 2;
    const float* W = (k < K) ? Wl : Wr;
    int kb = (k < K) ? k : k - K;
    float v0 = W[kb * 256 + n];
    float v1 = W[(kb + 1) * 256 + n];
    __nv_bfloat162 h = __floats2bfloat162_rn(v0, v1);
    float2 f = __bfloat1622float2(h);
    __nv_bfloat162 l = __floats2bfloat162_rn(v0 - f.x, v1 - f.y);

    int chunk = k >> 6;
    int kk = k & 63;
    int kstep = kk >> 4, kk16 = kk & 15;
    int t = (kk16 >> 1) & 3, regk = kk16 >> 3;
    int g = n & 7, ntile = n >> 3;
    size_t off = (size_t)chunk * 65536 + (size_t)kstep * 8192 + ntile * 256 +
                 (g * 4 + t) * 8 + regk * 4;
    *(uint32_t*)(wB + off) = *(uint32_t*)&h;           // sub0 = hi
    *(uint32_t*)(wB + off + 32768) = *(uint32_t*)&l;   // sub1 = lo
}

// ---------------- HMMA fused SAGE GEMM (full-width BN=256) -------------------
// out = act( [agg/max(cnt,1) | xt] @ W' + b )
// split-bf16: Ah*Wh + Al*Wh + Ah*Wl. CTA tile 128x256, 8 warps 2x4,
// warp tile 64x64. K chunks of 64 fp32; double-buffered 96KB stages
// (A frag 32KB + B frag 64KB). cp.async for B (contiguous 64KB copy),
// reg prefetch + in-reg bf16 split for A.
template <int K, bool RELU>
__global__ __launch_bounds__(256, 1) void mma_gemm(
    const float* __restrict__ agg, const float* __restrict__ cnt,
    const float* __restrict__ xt, const uint8_t* __restrict__ wB,
    const float* __restrict__ bias, float* __restrict__ out) {
    constexpr int CH = (2 * K) / 64;
    constexpr int STG = 98304;
    extern __shared__ char sm[];
    __shared__ float sInv[128];
    __shared__ float sBias[256];

    const int tid = threadIdx.x;
    const int lane = tid & 31;
    const int wid = tid >> 5;
    const int warp_m = wid & 1;
    const int warp_n = wid >> 1;
    const int m0 = blockIdx.x * 128;

    if (tid < 128) sInv[tid] = 1.0f / fmaxf(cnt[m0 + tid], 1.0f);
    sBias[tid] = bias[tid];

    const int row = tid >> 1;
    const int kcol0 = (tid & 1) * 32;
    const int mtile = row >> 4;
    const int gr = row & 7;
    const int regm = (row >> 3) & 1;

    // ---- A prefetch chunk 0 ----
    float4 ar[8];
    {
        const float4* p = (const float4*)(agg + (size_t)(m0 + row) * K + kcol0);
#pragma unroll
        for (int i = 0; i < 8; i++) ar[i] = p[i];
    }
    // ---- B cp.async chunk 0 -> stage 0 (contiguous 64KB) ----
    {
        char* dst = sm + 32768 + tid * 16;
        const uint8_t* src = wB + tid * 16;
#pragma unroll
        for (int blk = 0; blk < 16; blk++)
            cp_async16(smem_u32(dst + blk * 4096), src + blk * 4096);
        asm volatile("cp.async.commit_group;");
    }

    float acc[4][8][4];
#pragma unroll
    for (int a = 0; a < 4; a++)
#pragma unroll
        for (int b = 0; b < 8; b++)
#pragma unroll
            for (int c = 0; c < 4; c++) acc[a][b][c] = 0.0f;

    __syncthreads();  // sInv ready

    for (int c = 0; c < CH; c++) {
        const int s = c & 1;
        char* As = sm + s * STG;
        char* Bs = As + 32768;

        // ---- convert + store A into fragment layout (hi 16KB, lo +16KB) ----
        const float sc = (c * 64 < K) ? sInv[row] : 1.0f;
#pragma unroll
        for (int i = 0; i < 8; i++) {
            float x0 = ar[i].x * sc, x1 = ar[i].y * sc;
            float x2 = ar[i].z * sc, x3 = ar[i].w * sc;
#pragma unroll
            for (int j = 0; j < 2; j++) {
                float lo = j ? x2 : x0, hi = j ? x3 : x1;
                int k = kcol0 + 4 * i + 2 * j;
                int ks = k >> 4, kk16 = k & 15;
                int t = (kk16 >> 1) & 3, regk = kk16 >> 3;
                int off = ((ks * 8 + mtile) * 32 + (gr * 4 + t)) * 16 +
                          (regm + 2 * regk) * 4;
                __nv_bfloat162 h = __floats2bfloat162_rn(lo, hi);
                float2 f = __bfloat1622float2(h);
                __nv_bfloat162 l = __floats2bfloat162_rn(lo - f.x, hi - f.y);
                *(uint32_t*)(As + off) = *(uint32_t*)&h;
                *(uint32_t*)(As + 16384 + off) = *(uint32_t*)&l;
            }
        }

        // ---- prefetch next A ----
        if (c + 1 < CH) {
            int cc = (c + 1) * 64;
            bool ph = cc < K;
            const float* src = ph ? agg : xt;
            int kb = ph ? cc : cc - K;
            const float4* p =
                (const float4*)(src + (size_t)(m0 + row) * K + kb + kcol0);
#pragma unroll
            for (int i = 0; i < 8; i++) ar[i] = p[i];
        }
        // ---- cp.async next B ----
        if (c + 1 < CH) {
            char* dst = sm + (s ^ 1) * STG + 32768 + tid * 16;
            const uint8_t* src = wB + (size_t)(c + 1) * 65536 + tid * 16;
#pragma unroll
            for (int blk = 0; blk < 16; blk++)
                cp_async16(smem_u32(dst + blk * 4096), src + blk * 4096);
            asm volatile("cp.async.commit_group;");
            asm volatile("cp.async.wait_group 1;");
        } else {
            asm volatile("cp.async.wait_group 0;");
        }
        __syncthreads();

        // ---- MMA: products (Ah,Wh), (Al,Wh), (Ah,Wl) ----
#pragma unroll
        for (int p = 0; p < 3; p++) {
            const char* Ab = As + ((p == 1) ? 16384 : 0);
            const char* Bb = Bs + ((p == 2) ? 32768 : 0);
#pragma unroll
            for (int ks = 0; ks < 4; ks++) {
                uint4 a[4];
#pragma unroll
                for (int mt = 0; mt < 4; mt++)
                    a[mt] = *(const uint4*)(
                        Ab + ((ks * 8 + warp_m * 4 + mt) * 32 + lane) * 16);
#pragma unroll
                for (int nt = 0; nt < 8; nt++) {
                    uint2 b = *(const uint2*)(
                        Bb + (size_t)ks * 8192 +
                        ((warp_n * 8 + nt) * 32 + lane) * 8);
#pragma unroll
                    for (int mt = 0; mt < 4; mt++) mma16816(acc[mt][nt], a[mt], b);
                }
            }
        }
        __syncthreads();
    }

    // ---- epilogue ----
    const int tg = lane >> 2;
    const int tt = lane & 3;
#pragma unroll
    for (int mt = 0; mt < 4; mt++) {
        int r0 = m0 + warp_m * 64 + mt * 16 + tg;
#pragma unroll
        for (int nt = 0; nt < 8; nt++) {
            int ci = warp_n * 64 + nt * 8 + tt * 2;
            float b0v = sBias[ci], b1v = sBias[ci + 1];
            float v0 = acc[mt][nt][0] + b0v;
            float v1 = acc[mt][nt][1] + b1v;
            float v2 = acc[mt][nt][2] + b0v;
            float v3 = acc[mt][nt][3] + b1v;
            if (RELU) {
                v0 = fmaxf(v0, 0.f); v1 = fmaxf(v1, 0.f);
                v2 = fmaxf(v2, 0.f); v3 = fmaxf(v3, 0.f);
            }
            *(float2*)(out + (size_t)r0 * 256 + ci) = make_float2(v0, v1);
            *(float2*)(out + (size_t)(r0 + 8) * 256 + ci) = make_float2(v2, v3);
        }
    }
}

// ---------------- final layer: small GEMM + log_softmax fused ---------------
__global__ void final_kernel(const float* __restrict__ agg,
                             const float* __restrict__ cnt,
                             const float* __restrict__ xt,
                             const float* __restrict__ Wl,
                             const float* __restrict__ Wr,
                             const float* __restrict__ bias,
                             float* __restrict__ out) {
    __shared__ float sA[2 * C_HID];
    __shared__ float sred[64];
    int m = blockIdx.x;
    int tid = threadIdx.x;

    float invc = 1.0f / fmaxf(cnt[m], 1.0f);
    for (int j = tid; j < C_HID; j += 64) {
        sA[j] = agg[(size_t)m * C_HID + j] * invc;
        sA[C_HID + j] = xt[(size_t)m * C_HID + j];
    }
    __syncthreads();

    float z = -1e30f;
    if (tid < C_OUT) {
        float a = bias[tid];
        for (int k = 0; k < C_HID; k++) a = fmaf(sA[k], Wl[k * C_OUT + tid], a);
        for (int k = 0; k < C_HID; k++)
            a = fmaf(sA[C_HID + k], Wr[k * C_OUT + tid], a);
        z = a;
    }

    sred[tid] = z;
    __syncthreads();
    for (int s = 32; s > 0; s >>= 1) {
        if (tid < s) sred[tid] = fmaxf(sred[tid], sred[tid + s]);
        __syncthreads();
    }
    float mx = sred[0];
    __syncthreads();
    sred[tid] = (tid < C_OUT) ? expf(z - mx) : 0.0f;
    __syncthreads();
    for (int s = 32; s > 0; s >>= 1) {
        if (tid < s) sred[tid] += sred[tid + s];
        __syncthreads();
    }
    float lse = logf(sred[0]) + mx;
    if (tid < C_OUT) out[m * C_OUT + tid] = z - lse;
}

// ---------------- launch -----------------------------------------------------
extern "C" void kernel_launch(void* const* d_in, const int* in_sizes, int n_in,
                              void* d_out, int out_size) {
    const float* x   = (const float*)d_in[0];
    const int*  ei0  = (const int*)d_in[1];
    const int*  ei1  = (const int*)d_in[2];
    const int*  ei2  = (const int*)d_in[3];
    const float* Wl0 = (const float*)d_in[4];
    const float* Wr0 = (const float*)d_in[5];
    const float* b0  = (const float*)d_in[6];
    const float* Wl1 = (const float*)d_in[7];
    const float* Wr1 = (const float*)d_in[8];
    const float* b1  = (const float*)d_in[9];
    const float* Wl2 = (const float*)d_in[10];
    const float* Wr2 = (const float*)d_in[11];
    const float* b2  = (const float*)d_in[12];

    int E0 = in_sizes[1] / 2;
    int E1 = in_sizes[2] / 2;
    int E2 = in_sizes[3] / 2;

    float *agg0, *cnt0, *h0, *agg1, *cnt1, *h1, *agg2, *cnt2;
    uint8_t *wB0, *wB1;
    cudaGetSymbolAddress((void**)&agg0, g_agg0);
    cudaGetSymbolAddress((void**)&cnt0, g_cnt0);
    cudaGetSymbolAddress((void**)&h0,   g_h0);
    cudaGetSymbolAddress((void**)&agg1, g_agg1);
    cudaGetSymbolAddress((void**)&cnt1, g_cnt1);
    cudaGetSymbolAddress((void**)&h1,   g_h1);
    cudaGetSymbolAddress((void**)&agg2, g_agg2);
    cudaGetSymbolAddress((void**)&cnt2, g_cnt2);
    cudaGetSymbolAddress((void**)&wB0,  g_wB0);
    cudaGetSymbolAddress((void**)&wB1,  g_wB1);

    const int SMEM_MM = 2 * 98304;
    cudaFuncSetAttribute(mma_gemm<C_IN, true>,
                         cudaFuncAttributeMaxDynamicSharedMemorySize, SMEM_MM);
    cudaFuncSetAttribute(mma_gemm<C_HID, true>,
                         cudaFuncAttributeMaxDynamicSharedMemorySize, SMEM_MM);

    float* out = (float*)d_out;

    // weight prep (independent of data path)
    prep_w<<<(C_IN * 256 + 255) / 256, 256>>>(Wl0, Wr0, C_IN, wB0);
    prep_w<<<(C_HID * 256 + 255) / 256, 256>>>(Wl1, Wr1, C_HID, wB1);

    // ---- layer 0 ----
    {
        int n4 = N1 * C_IN / 4;
        zero_kernel<<<(n4 + 255) / 256, 256>>>((float4*)agg0, n4);
        zero_kernel<<<(N1 / 4 + 255) / 256, 256>>>((float4*)cnt0, N1 / 4);
        int warps0 = (E0 + 3) / 4;
        scatter_kernel<C_IN><<<(warps0 * 32 + 255) / 256, 256>>>(
            x, ei0, E0, agg0, cnt0);
        mma_gemm<C_IN, true><<<N1 / 128, 256, SMEM_MM>>>(
            agg0, cnt0, x, wB0, b0, h0);
    }
    // ---- layer 1 ----
    {
        int n4 = N2 * C_HID / 4;
        zero_kernel<<<(n4 + 255) / 256, 256>>>((float4*)agg1, n4);
        zero_kernel<<<(N2 / 4 + 255) / 256, 256>>>((float4*)cnt1, N2 / 4);
        int warps1 = (E1 + 3) / 4;
        scatter_kernel<C_HID><<<(warps1 * 32 + 255) / 256, 256>>>(
            h0, ei1, E1, agg1, cnt1);
        mma_gemm<C_HID, true><<<N2 / 128, 256, SMEM_MM>>>(
            agg1, cnt1, h0, wB1, b1, h1);
    }
    // ---- layer 2 + log_softmax ----
    {
        int n4 = N3 * C_HID / 4;
        zero_kernel<<<(n4 + 255) / 256, 256>>>((float4*)agg2, n4);
        zero_kernel<<<(N3 / 4 + 255) / 256, 256>>>((float4*)cnt2, N3 / 4);
        int warps2 = (E2 + 3) / 4;
        scatter_kernel<C_HID><<<(warps2 * 32 + 255) / 256, 256>>>(
            h1, ei2, E2, agg2, cnt2);
        final_kernel<<<N3, 64>>>(agg2, cnt2, h1, Wl2, Wr2, b2, out);
    }
}

// round 7
// speedup vs baseline: 1.4724x; 1.0303x over previous
#include <cuda_runtime.h>
#include <cuda_bf16.h>
#include <math.h>
#include <stdint.h>

#define N0 1362944
#define N1 123904
#define N2 11264
#define N3 1024
#define C_IN 128
#define C_HID 256
#define C_OUT 47
#define E0MAX (10 * N1 + 1024)

// ---------------- scratch (device globals; no allocation allowed) ----------
__device__ float g_agg0[N1 * C_IN];
__device__ float g_h0[N1 * C_HID];
__device__ float g_agg1[N2 * C_HID];
__device__ float g_h1[N2 * C_HID];
__device__ float g_agg2[N3 * C_HID];
// CSR scratch (sized for layer 0, reused by all layers)
__device__ int g_deg[N1];          // degree / cursor
__device__ int g_rs[N1 + 1];       // row starts (exclusive scan)
__device__ int g_bsum[256];        // block sums for scan
__device__ int g_csr[E0MAX];       // per-slot source node id
// pre-fragmented bf16 weights: per 64-fp32-k chunk (64KB contiguous):
//   [hi 32KB: kstep4 x (ntile32 x lane32 x 8B)][lo 32KB: same]
__device__ uint8_t g_wB0[4 * 65536];   // layer0: 4 chunks
__device__ uint8_t g_wB1[8 * 65536];   // layer1: 8 chunks

// ---------------- helpers ---------------------------------------------------
__device__ __forceinline__ uint32_t smem_u32(const void* p) {
    uint32_t a;
    asm("{ .reg .u64 t; cvta.to.shared.u64 t, %1; cvt.u32.u64 %0, t; }"
        : "=r"(a) : "l"(p));
    return a;
}
__device__ __forceinline__ void cp_async16(uint32_t dst, const void* src) {
    asm volatile("cp.async.ca.shared.global [%0], [%1], 16;"
                 :: "r"(dst), "l"(src) : "memory");
}
__device__ __forceinline__ void mma16816(float* d, const uint4& a, const uint2& b) {
    asm volatile(
        "mma.sync.aligned.m16n8k16.row.col.f32.bf16.bf16.f32 "
        "{%0,%1,%2,%3}, {%4,%5,%6,%7}, {%8,%9}, {%0,%1,%2,%3};"
        : "+f"(d[0]), "+f"(d[1]), "+f"(d[2]), "+f"(d[3])
        : "r"(a.x), "r"(a.y), "r"(a.z), "r"(a.w), "r"(b.x), "r"(b.y));
}

// ---------------- zero ------------------------------------------------------
__global__ void zero_kernel(float4* __restrict__ p, int n4) {
    int i = blockIdx.x * blockDim.x + threadIdx.x;
    int stride = gridDim.x * blockDim.x;
    float4 z = make_float4(0.f, 0.f, 0.f, 0.f);
    for (; i < n4; i += stride) p[i] = z;
}

// ---------------- CSR build --------------------------------------------------
__global__ void hist_kernel(const int* __restrict__ ei, int E,
                            int* __restrict__ deg) {
    int e = blockIdx.x * blockDim.x + threadIdx.x;
    if (e < E) atomicAdd(&deg[__ldg(&ei[E + e])], 1);
}

// per-block inclusive scan (Hillis-Steele, 1024 elems) -> exclusive out
__global__ void scan_block(const int* __restrict__ deg, int* __restrict__ rs,
                           int* __restrict__ bsum, int n) {
    __shared__ int s[1024];
    int t = threadIdx.x;
    int i = blockIdx.x * 1024 + t;
    int v = (i < n) ? deg[i] : 0;
    s[t] = v;
    __syncthreads();
#pragma unroll
    for (int off = 1; off < 1024; off <<= 1) {
        int tmp = (t >= off) ? s[t - off] : 0;
        __syncthreads();
        s[t] += tmp;
        __syncthreads();
    }
    if (i < n) rs[i] = s[t] - v;          // exclusive
    if (t == 1023) bsum[blockIdx.x] = s[t];
}

// exclusive scan of up to 128 block sums, in place (1 block, 128 thr)
__global__ void scan_sums(int* __restrict__ bsum, int B) {
    __shared__ int s[128];
    int t = threadIdx.x;
    int v = (t < B) ? bsum[t] : 0;
    s[t] = v;
    __syncthreads();
#pragma unroll
    for (int off = 1; off < 128; off <<= 1) {
        int tmp = (t >= off) ? s[t - off] : 0;
        __syncthreads();
        s[t] += tmp;
        __syncthreads();
    }
    if (t < B) bsum[t] = s[t] - v;
}

__global__ void add_off(int* __restrict__ rs, const int* __restrict__ bsum,
                        int n, int E) {
    int i = blockIdx.x * 1024 + threadIdx.x;
    if (i < n) rs[i] += bsum[blockIdx.x];
    if (i == 0) rs[n] = E;
}

__global__ void fill_kernel(const int* __restrict__ ei, int E,
                            const int* __restrict__ rs, int* __restrict__ cur,
                            int* __restrict__ csr) {
    int e = blockIdx.x * blockDim.x + threadIdx.x;
    if (e >= E) return;
    int s = __ldg(&ei[e]);
    int t = __ldg(&ei[E + e]);
    int slot = rs[t] + atomicAdd(&cur[t], 1);
    csr[slot] = s;
}

// ---------------- atomic-free aggregation: warp per target ------------------
// writes agg[t] = mean(feat[src] for src in nbrs(t))  (0 if no nbrs)
template <int C>
__global__ void agg_csr(const float* __restrict__ feat,
                        const int* __restrict__ rs, const int* __restrict__ csr,
                        int n, float* __restrict__ agg) {
    constexpr int R = C / 128;
    int warp = (blockIdx.x * blockDim.x + threadIdx.x) >> 5;
    int lane = threadIdx.x & 31;
    if (warp >= n) return;
    int start = __ldg(&rs[warp]);
    int end = __ldg(&rs[warp + 1]);

    float4 acc[R];
#pragma unroll
    for (int r = 0; r < R; r++) acc[r] = make_float4(0.f, 0.f, 0.f, 0.f);

    int e = start;
    for (; e + 4 <= end; e += 4) {
        int s0 = __ldg(&csr[e + 0]);
        int s1 = __ldg(&csr[e + 1]);
        int s2 = __ldg(&csr[e + 2]);
        int s3 = __ldg(&csr[e + 3]);
        float4 v0[R], v1[R], v2[R], v3[R];
#pragma unroll
        for (int r = 0; r < R; r++) {
            v0[r] = __ldg((const float4*)(feat + (size_t)s0 * C) + lane + 32 * r);
            v1[r] = __ldg((const float4*)(feat + (size_t)s1 * C) + lane + 32 * r);
            v2[r] = __ldg((const float4*)(feat + (size_t)s2 * C) + lane + 32 * r);
            v3[r] = __ldg((const float4*)(feat + (size_t)s3 * C) + lane + 32 * r);
        }
#pragma unroll
        for (int r = 0; r < R; r++) {
            acc[r].x += v0[r].x + v1[r].x + v2[r].x + v3[r].x;
            acc[r].y += v0[r].y + v1[r].y + v2[r].y + v3[r].y;
            acc[r].z += v0[r].z + v1[r].z + v2[r].z + v3[r].z;
            acc[r].w += v0[r].w + v1[r].w + v2[r].w + v3[r].w;
        }
    }
    for (; e < end; e++) {
        int s = __ldg(&csr[e]);
#pragma unroll
        for (int r = 0; r < R; r++) {
            float4 v = __ldg((const float4*)(feat + (size_t)s * C) + lane + 32 * r);
            acc[r].x += v.x; acc[r].y += v.y; acc[r].z += v.z; acc[r].w += v.w;
        }
    }

    float inv = 1.0f / (float)max(end - start, 1);
    float4* orow = (float4*)(agg + (size_t)warp * C) + lane;
#pragma unroll
    for (int r = 0; r < R; r++) {
        acc[r].x *= inv; acc[r].y *= inv; acc[r].z *= inv; acc[r].w *= inv;
        orow[32 * r] = acc[r];
    }
}

// ---------------- weight prep: stack, split bf16 hi/lo, fragment-pack -------
__global__ void prep_w(const float* __restrict__ Wl, const float* __restrict__ Wr,
                       int K, uint8_t* __restrict__ wB) {
    int idx = blockIdx.x * blockDim.x + threadIdx.x;
    if (idx >= K * 256) return;          // K pairs over 2K stacked rows
    int kp = idx >> 8, n = idx & 255;
    int k = kp * 2;
    const float* W = (k < K) ? Wl : Wr;
    int kb = (k < K) ? k : k - K;
    float v0 = W[kb * 256 + n];
    float v1 = W[(kb + 1) * 256 + n];
    __nv_bfloat162 h = __floats2bfloat162_rn(v0, v1);
    float2 f = __bfloat1622float2(h);
    __nv_bfloat162 l = __floats2bfloat162_rn(v0 - f.x, v1 - f.y);

    int chunk = k >> 6;
    int kk = k & 63;
    int kstep = kk >> 4, kk16 = kk & 15;
    int t = (kk16 >> 1) & 3, regk = kk16 >> 3;
    int g = n & 7, ntile = n >> 3;
    size_t off = (size_t)chunk * 65536 + (size_t)kstep * 8192 + ntile * 256 +
                 (g * 4 + t) * 8 + regk * 4;
    *(uint32_t*)(wB + off) = *(uint32_t*)&h;           // sub0 = hi
    *(uint32_t*)(wB + off + 32768) = *(uint32_t*)&l;   // sub1 = lo
}

// ---------------- HMMA fused SAGE GEMM (BN=256, agg pre-scaled) -------------
// out = act( [agg | xt] @ W' + b )
template <int K, bool RELU>
__global__ __launch_bounds__(256, 1) void mma_gemm(
    const float* __restrict__ agg, const float* __restrict__ xt,
    const uint8_t* __restrict__ wB, const float* __restrict__ bias,
    float* __restrict__ out) {
    constexpr int CH = (2 * K) / 64;
    constexpr int STG = 98304;
    extern __shared__ char sm[];
    __shared__ float sBias[256];

    const int tid = threadIdx.x;
    const int lane = tid & 31;
    const int wid = tid >> 5;
    const int warp_m = wid & 1;
    const int warp_n = wid >> 1;
    const int m0 = blockIdx.x * 128;

    sBias[tid] = bias[tid];

    const int row = tid >> 1;
    const int kcol0 = (tid & 1) * 32;
    const int mtile = row >> 4;
    const int gr = row & 7;
    const int regm = (row >> 3) & 1;

    // ---- A prefetch chunk 0 ----
    float4 ar[8];
    {
        const float4* p = (const float4*)(agg + (size_t)(m0 + row) * K + kcol0);
#pragma unroll
        for (int i = 0; i < 8; i++) ar[i] = p[i];
    }
    // ---- B cp.async chunk 0 -> stage 0 (contiguous 64KB) ----
    {
        char* dst = sm + 32768 + tid * 16;
        const uint8_t* src = wB + tid * 16;
#pragma unroll
        for (int blk = 0; blk < 16; blk++)
            cp_async16(smem_u32(dst + blk * 4096), src + blk * 4096);
        asm volatile("cp.async.commit_group;");
    }

    float acc[4][8][4];
#pragma unroll
    for (int a = 0; a < 4; a++)
#pragma unroll
        for (int b = 0; b < 8; b++)
#pragma unroll
            for (int c = 0; c < 4; c++) acc[a][b][c] = 0.0f;

    __syncthreads();

    for (int c = 0; c < CH; c++) {
        const int s = c & 1;
        char* As = sm + s * STG;
        char* Bs = As + 32768;

        // ---- convert + store A into fragment layout (hi 16KB, lo +16KB) ----
#pragma unroll
        for (int i = 0; i < 8; i++) {
            float x0 = ar[i].x, x1 = ar[i].y, x2 = ar[i].z, x3 = ar[i].w;
#pragma unroll
            for (int j = 0; j < 2; j++) {
                float lo = j ? x2 : x0, hi = j ? x3 : x1;
                int k = kcol0 + 4 * i + 2 * j;
                int ks = k >> 4, kk16 = k & 15;
                int t = (kk16 >> 1) & 3, regk = kk16 >> 3;
                int off = ((ks * 8 + mtile) * 32 + (gr * 4 + t)) * 16 +
                          (regm + 2 * regk) * 4;
                __nv_bfloat162 h = __floats2bfloat162_rn(lo, hi);
                float2 f = __bfloat1622float2(h);
                __nv_bfloat162 l = __floats2bfloat162_rn(lo - f.x, hi - f.y);
                *(uint32_t*)(As + off) = *(uint32_t*)&h;
                *(uint32_t*)(As + 16384 + off) = *(uint32_t*)&l;
            }
        }

        // ---- prefetch next A ----
        if (c + 1 < CH) {
            int cc = (c + 1) * 64;
            bool ph = cc < K;
            const float* src = ph ? agg : xt;
            int kb = ph ? cc : cc - K;
            const float4* p =
                (const float4*)(src + (size_t)(m0 + row) * K + kb + kcol0);
#pragma unroll
            for (int i = 0; i < 8; i++) ar[i] = p[i];
        }
        // ---- cp.async next B ----
        if (c + 1 < CH) {
            char* dst = sm + (s ^ 1) * STG + 32768 + tid * 16;
            const uint8_t* src = wB + (size_t)(c + 1) * 65536 + tid * 16;
#pragma unroll
            for (int blk = 0; blk < 16; blk++)
                cp_async16(smem_u32(dst + blk * 4096), src + blk * 4096);
            asm volatile("cp.async.commit_group;");
            asm volatile("cp.async.wait_group 1;");
        } else {
            asm volatile("cp.async.wait_group 0;");
        }
        __syncthreads();

        // ---- MMA: products (Ah,Wh), (Al,Wh), (Ah,Wl) ----
#pragma unroll
        for (int p = 0; p < 3; p++) {
            const char* Ab = As + ((p == 1) ? 16384 : 0);
            const char* Bb = Bs + ((p == 2) ? 32768 : 0);
#pragma unroll
            for (int ks = 0; ks < 4; ks++) {
                uint4 a[4];
#pragma unroll
                for (int mt = 0; mt < 4; mt++)
                    a[mt] = *(const uint4*)(
                        Ab + ((ks * 8 + warp_m * 4 + mt) * 32 + lane) * 16);
#pragma unroll
                for (int nt = 0; nt < 8; nt++) {
                    uint2 b = *(const uint2*)(
                        Bb + (size_t)ks * 8192 +
                        ((warp_n * 8 + nt) * 32 + lane) * 8);
#pragma unroll
                    for (int mt = 0; mt < 4; mt++) mma16816(acc[mt][nt], a[mt], b);
                }
            }
        }
        __syncthreads();
    }

    // ---- epilogue ----
    const int tg = lane >> 2;
    const int tt = lane & 3;
#pragma unroll
    for (int mt = 0; mt < 4; mt++) {
        int r0 = m0 + warp_m * 64 + mt * 16 + tg;
#pragma unroll
        for (int nt = 0; nt < 8; nt++) {
            int ci = warp_n * 64 + nt * 8 + tt * 2;
            float b0v = sBias[ci], b1v = sBias[ci + 1];
            float v0 = acc[mt][nt][0] + b0v;
            float v1 = acc[mt][nt][1] + b1v;
            float v2 = acc[mt][nt][2] + b0v;
            float v3 = acc[mt][nt][3] + b1v;
            if (RELU) {
                v0 = fmaxf(v0, 0.f); v1 = fmaxf(v1, 0.f);
                v2 = fmaxf(v2, 0.f); v3 = fmaxf(v3, 0.f);
            }
            *(float2*)(out + (size_t)r0 * 256 + ci) = make_float2(v0, v1);
            *(float2*)(out + (size_t)(r0 + 8) * 256 + ci) = make_float2(v2, v3);
        }
    }
}

// ---------------- final layer: small GEMM + log_softmax fused ---------------
__global__ void final_kernel(const float* __restrict__ agg,
                             const float* __restrict__ xt,
                             const float* __restrict__ Wl,
                             const float* __restrict__ Wr,
                             const float* __restrict__ bias,
                             float* __restrict__ out) {
    __shared__ float sA[2 * C_HID];
    __shared__ float sred[64];
    int m = blockIdx.x;
    int tid = threadIdx.x;

    for (int j = tid; j < C_HID; j += 64) {
        sA[j] = agg[(size_t)m * C_HID + j];
        sA[C_HID + j] = xt[(size_t)m * C_HID + j];
    }
    __syncthreads();

    float z = -1e30f;
    if (tid < C_OUT) {
        float a = bias[tid];
        for (int k = 0; k < C_HID; k++) a = fmaf(sA[k], Wl[k * C_OUT + tid], a);
        for (int k = 0; k < C_HID; k++)
            a = fmaf(sA[C_HID + k], Wr[k * C_OUT + tid], a);
        z = a;
    }

    sred[tid] = z;
    __syncthreads();
    for (int s = 32; s > 0; s >>= 1) {
        if (tid < s) sred[tid] = fmaxf(sred[tid], sred[tid + s]);
        __syncthreads();
    }
    float mx = sred[0];
    __syncthreads();
    sred[tid] = (tid < C_OUT) ? expf(z - mx) : 0.0f;
    __syncthreads();
    for (int s = 32; s > 0; s >>= 1) {
        if (tid < s) sred[tid] += sred[tid + s];
        __syncthreads();
    }
    float lse = logf(sred[0]) + mx;
    if (tid < C_OUT) out[m * C_OUT + tid] = z - lse;
}

// ---------------- host-side CSR build + aggregate ----------------------------
static void build_and_aggregate(const float* feat, const int* ei, int E, int n,
                                int C, int* deg, int* rs, int* bsum, int* csr,
                                float* agg) {
    int B = (n + 1023) / 1024;
    zero_kernel<<<(n / 4 + 255) / 256, 256>>>((float4*)deg, n / 4);
    hist_kernel<<<(E + 255) / 256, 256>>>(ei, E, deg);
    scan_block<<<B, 1024>>>(deg, rs, bsum, n);
    scan_sums<<<1, 128>>>(bsum, B);
    add_off<<<B, 1024>>>(rs, bsum, n, E);
    zero_kernel<<<(n / 4 + 255) / 256, 256>>>((float4*)deg, n / 4);
    fill_kernel<<<(E + 255) / 256, 256>>>(ei, E, rs, deg, csr);
    if (C == 128)
        agg_csr<128><<<(n + 7) / 8, 256>>>(feat, rs, csr, n, agg);
    else
        agg_csr<256><<<(n + 7) / 8, 256>>>(feat, rs, csr, n, agg);
}

// ---------------- launch -----------------------------------------------------
extern "C" void kernel_launch(void* const* d_in, const int* in_sizes, int n_in,
                              void* d_out, int out_size) {
    const float* x   = (const float*)d_in[0];
    const int*  ei0  = (const int*)d_in[1];
    const int*  ei1  = (const int*)d_in[2];
    const int*  ei2  = (const int*)d_in[3];
    const float* Wl0 = (const float*)d_in[4];
    const float* Wr0 = (const float*)d_in[5];
    const float* b0  = (const float*)d_in[6];
    const float* Wl1 = (const float*)d_in[7];
    const float* Wr1 = (const float*)d_in[8];
    const float* b1  = (const float*)d_in[9];
    const float* Wl2 = (const float*)d_in[10];
    const float* Wr2 = (const float*)d_in[11];
    const float* b2  = (const float*)d_in[12];

    int E0 = in_sizes[1] / 2;
    int E1 = in_sizes[2] / 2;
    int E2 = in_sizes[3] / 2;

    float *agg0, *h0, *agg1, *h1, *agg2;
    int *deg, *rs, *bsum, *csr;
    uint8_t *wB0, *wB1;
    cudaGetSymbolAddress((void**)&agg0, g_agg0);
    cudaGetSymbolAddress((void**)&h0,   g_h0);
    cudaGetSymbolAddress((void**)&agg1, g_agg1);
    cudaGetSymbolAddress((void**)&h1,   g_h1);
    cudaGetSymbolAddress((void**)&agg2, g_agg2);
    cudaGetSymbolAddress((void**)&deg,  g_deg);
    cudaGetSymbolAddress((void**)&rs,   g_rs);
    cudaGetSymbolAddress((void**)&bsum, g_bsum);
    cudaGetSymbolAddress((void**)&csr,  g_csr);
    cudaGetSymbolAddress((void**)&wB0,  g_wB0);
    cudaGetSymbolAddress((void**)&wB1,  g_wB1);

    const int SMEM_MM = 2 * 98304;
    cudaFuncSetAttribute(mma_gemm<C_IN, true>,
                         cudaFuncAttributeMaxDynamicSharedMemorySize, SMEM_MM);
    cudaFuncSetAttribute(mma_gemm<C_HID, true>,
                         cudaFuncAttributeMaxDynamicSharedMemorySize, SMEM_MM);

    float* out = (float*)d_out;

    // weight prep (independent of data path)
    prep_w<<<(C_IN * 256 + 255) / 256, 256>>>(Wl0, Wr0, C_IN, wB0);
    prep_w<<<(C_HID * 256 + 255) / 256, 256>>>(Wl1, Wr1, C_HID, wB1);

    // ---- layer 0 ----
    build_and_aggregate(x, ei0, E0, N1, C_IN, deg, rs, bsum, csr, agg0);
    mma_gemm<C_IN, true><<<N1 / 128, 256, SMEM_MM>>>(agg0, x, wB0, b0, h0);

    // ---- layer 1 ----
    build_and_aggregate(h0, ei1, E1, N2, C_HID, deg, rs, bsum, csr, agg1);
    mma_gemm<C_HID, true><<<N2 / 128, 256, SMEM_MM>>>(agg1, h0, wB1, b1, h1);

    // ---- layer 2 + log_softmax ----
    build_and_aggregate(h1, ei2, E2, N3, C_HID, deg, rs, bsum, csr, agg2);
    final_kernel<<<N3, 64>>>(agg2, h1, Wl2, Wr2, b2, out);
}